// round 11
// baseline (speedup 1.0000x reference)
#include <cuda_runtime.h>
#include <cuda_fp16.h>
#include <math.h>
#include <stdint.h>

#define HEADS 8
#define DIMH  64
#define SEQ   16
#define CH    512
#define BATCH 2048              // b*h*w
#define MROWS (BATCH*SEQ)       // 32768
#define QKVN  1536
#define MEM   4
#define KVLEN 20
#define MP_INV 1.3130643286f    // 1/sqrt(0.58)

typedef __half f16;

// ------------------------- scratch (device globals) -------------------------
__device__ float g_Y   [(size_t)MROWS*CH];
__device__ float g_RES [(size_t)MROWS*CH];
__device__ float g_P   [(size_t)MROWS*CH];
__device__ f16   g_QKVh[(size_t)MROWS*QKVN];
__device__ f16   g_Yh  [(size_t)MROWS*CH];
__device__ f16   g_ATh [(size_t)MROWS*CH];
__device__ f16   g_Wq [2*QKVN*CH];
__device__ f16   g_Wo [2*CH*CH];
__device__ f16   g_Wp [CH*CH];

// ------------------------- transpose in -------------------------------------
__global__ void transpose_in(const float* __restrict__ x,
                             float* __restrict__ Y, float* __restrict__ RES,
                             f16* __restrict__ Yh) {
    __shared__ float tile[32][33];
    const int b  = blockIdx.z;
    const int t  = blockIdx.y >> 5;
    const int i  = blockIdx.y & 31;
    const int c0 = blockIdx.x << 5;
    const int tx = threadIdx.x, ty = threadIdx.y;   // (32,8)

    const float* xp = x + (((size_t)(b*CH + c0)*SEQ + t)*32 + i)*32;
#pragma unroll
    for (int r = 0; r < 4; r++) {
        int cl = ty + r*8;
        tile[cl][tx] = xp[(size_t)cl*SEQ*32*32 + tx];
    }
    __syncthreads();
#pragma unroll
    for (int r = 0; r < 4; r++) {
        int j = ty + r*8;
        size_t off = ((size_t)(b*1024 + i*32 + j)*SEQ + t)*CH + c0 + tx;
        float v = tile[tx][j];
        Y[off] = v; RES[off] = v;
        Yh[off] = __float2half_rn(v);
    }
}

// ------------------ transpose out + final mp_add ----------------------------
__global__ void transpose_out(const float* __restrict__ P,
                              const float* __restrict__ RES,
                              float* __restrict__ out) {
    __shared__ float tile[32][33];
    const int b  = blockIdx.z;
    const int t  = blockIdx.y >> 5;
    const int i  = blockIdx.y & 31;
    const int c0 = blockIdx.x << 5;
    const int tx = threadIdx.x, ty = threadIdx.y;

#pragma unroll
    for (int r = 0; r < 4; r++) {
        int j = ty + r*8;
        size_t off = ((size_t)(b*1024 + i*32 + j)*SEQ + t)*CH + c0 + tx;
        tile[tx][j] = (P[off]*0.7f + RES[off]*0.3f) * MP_INV;
    }
    __syncthreads();
    float* op = out + (((size_t)(b*CH + c0)*SEQ + t)*32 + i)*32;
#pragma unroll
    for (int r = 0; r < 4; r++) {
        int cl = ty + r*8;
        op[(size_t)cl*SEQ*32*32 + tx] = tile[cl][tx];
    }
}

// ----------------- weight row l2norm -> fp16 --------------------------------
__global__ void rownorm(const float* __restrict__ src,
                        f16* __restrict__ dst,
                        const float* __restrict__ gain) {
    const int row = blockIdx.x;
    const int t   = threadIdx.x;            // 128 threads, K=512
    const float4 v = ((const float4*)(src + (size_t)row*CH))[t];
    float ss = v.x*v.x + v.y*v.y + v.z*v.z + v.w*v.w;
#pragma unroll
    for (int o = 16; o; o >>= 1) ss += __shfl_xor_sync(0xffffffffu, ss, o);
    __shared__ float red[4];
    __shared__ float sscale;
    if ((t & 31) == 0) red[t >> 5] = ss;
    __syncthreads();
    if (t == 0) {
        float tot = red[0] + red[1] + red[2] + red[3];
        float sc = 1.f / (fmaxf(sqrtf(tot), 1e-4f) * 22.627416998f); // sqrt(512)
        if (gain) sc *= gain[0];
        sscale = sc;
    }
    __syncthreads();
    const float sc = sscale;
    union { f16 b[4]; uint2 u; } H;
    H.b[0] = __float2half_rn(v.x*sc); H.b[1] = __float2half_rn(v.y*sc);
    H.b[2] = __float2half_rn(v.z*sc); H.b[3] = __float2half_rn(v.w*sc);
    *(uint2*)(dst + (size_t)row*CH + 4*t) = H.u;
}

// ==================== mma.sync fp16 GEMM =====================================
// C[M,N] = A[M,512] @ B[N,512]^T  (fp16 operands, fp32 accum).
// CTA tile 128x128, K-chunk 64 (128B rows, SW128), cp.async 3-stage,
// ONE __syncthreads per chunk. 8 warps 4(M)x2(N); warp tile 32x64. 2 CTAs/SM.
// MODE 0: write f16 Ch only. MODE 1: blend with fp32 C, write C + f16 Ch.
// MODE 2: write fp32 C only.

#define TILE_B 16384               // one 128row x 128B tile
#define STAGE  (2*TILE_B)          // A, B
#define GSMEM  (3*STAGE)           // 98304 (3 stages)

__device__ __forceinline__ uint32_t sw128(uint32_t o) { return o ^ ((o >> 3) & 0x70); }

__device__ __forceinline__ void cp16(uint32_t dst, const void* src) {
    asm volatile("cp.async.cg.shared.global [%0], [%1], 16;\n" :: "r"(dst), "l"(src));
}
#define CP_COMMIT() asm volatile("cp.async.commit_group;\n" ::: "memory")
#define CP_WAIT(n)  asm volatile("cp.async.wait_group %0;\n" :: "n"(n) : "memory")

__device__ __forceinline__ void ldsm4(uint32_t (&r)[4], uint32_t addr) {
    asm volatile("ldmatrix.sync.aligned.m8n8.x4.shared.b16 {%0,%1,%2,%3}, [%4];"
                 : "=r"(r[0]), "=r"(r[1]), "=r"(r[2]), "=r"(r[3]) : "r"(addr));
}

__device__ __forceinline__ void mma16816(float (&d)[4], const uint32_t (&a)[4],
                                         const uint32_t* b) {
    asm volatile(
        "mma.sync.aligned.m16n8k16.row.col.f32.f16.f16.f32 "
        "{%0,%1,%2,%3}, {%4,%5,%6,%7}, {%8,%9}, {%0,%1,%2,%3};"
        : "+f"(d[0]), "+f"(d[1]), "+f"(d[2]), "+f"(d[3])
        : "r"(a[0]), "r"(a[1]), "r"(a[2]), "r"(a[3]), "r"(b[0]), "r"(b[1]));
}

template<int MODE>
__global__ void __launch_bounds__(256, 2)
gemm_mma(const f16* __restrict__ Ah_, const f16* __restrict__ Bh_,
         float* __restrict__ C, f16* __restrict__ Ch,
         int N) {
    extern __shared__ char smem[];
    const uint32_t sb = (uint32_t)__cvta_generic_to_shared(smem);
    const int tid   = threadIdx.x;
    const int lane  = tid & 31;
    const int warp  = tid >> 5;
    const int warpM = warp & 3;          // 0..3  -> 32-row slab
    const int warpN = warp >> 2;         // 0..1  -> 64-col slab
    const int m0 = blockIdx.y * 128;
    const int n0 = blockIdx.x * 128;

    float acc[2][8][4];
#pragma unroll
    for (int i = 0; i < 2; i++)
#pragma unroll
        for (int j = 0; j < 8; j++)
#pragma unroll
            for (int e = 0; e < 4; e++) acc[i][j][e] = 0.f;

    // ldmatrix lane addressing (within a 128B-row SW128 tile)
    const int a_row  = (lane & 15);              // + frag*16
    const int a_byte = (lane >> 4) << 4;         // + ks*32
    const int b_row  = (lane & 7) + ((lane >> 4) << 3);   // + group*16
    const int b_byte = ((lane >> 3) & 1) << 4;   // + ks*32

    auto load_chunk = [&](int c, int buf) {
        const uint32_t bb = sb + buf*STAGE;
        const int k0 = c * 64;
#pragma unroll
        for (int i = tid; i < 1024; i += 256) {      // 128 rows x 8 segs
            int r = i >> 3, s = i & 7;
            uint32_t o = sw128(r*128 + s*16);
            cp16(bb + o,          Ah_ + (size_t)(m0 + r)*CH + k0 + s*8);
            cp16(bb + TILE_B + o, Bh_ + (size_t)(n0 + r)*CH + k0 + s*8);
        }
        CP_COMMIT();
    };

    load_chunk(0, 0);
    load_chunk(1, 1);

    for (int c = 0; c < 8; c++) {
        // chunk c complete after this wait (c+1 may still be in flight)
        if (c < 7) { CP_WAIT(1); } else { CP_WAIT(0); }
        __syncthreads();
        // safe: all warps finished compute(c-1) (reader of buf (c+2)%3) above
        if (c + 2 < 8) load_chunk(c + 2, (c + 2) % 3);

        const uint32_t bb = sb + (c % 3)*STAGE;
#pragma unroll
        for (int ks = 0; ks < 4; ks++) {
            const int kb = ks * 32;
            uint32_t ah[2][4];
#pragma unroll
            for (int mf = 0; mf < 2; mf++) {
                uint32_t ro = (uint32_t)(warpM*32 + mf*16 + a_row)*128 + kb + a_byte;
                ldsm4(ah[mf], bb + sw128(ro));
            }
            uint32_t bh[8][2];
#pragma unroll
            for (int g = 0; g < 4; g++) {
                uint32_t ro = (uint32_t)(warpN*64 + g*16 + b_row)*128 + kb + b_byte;
                uint32_t t[4];
                ldsm4(t, bb + TILE_B + sw128(ro));
                bh[2*g][0] = t[0]; bh[2*g][1] = t[1];
                bh[2*g+1][0] = t[2]; bh[2*g+1][1] = t[3];
            }
#pragma unroll
            for (int mf = 0; mf < 2; mf++)
#pragma unroll
                for (int nf = 0; nf < 8; nf++)
                    mma16816(acc[mf][nf], ah[mf], bh[nf]);
        }
    }

    // ------------------------------ epilogue --------------------------------
    const int mr = m0 + warpM*32 + (lane >> 2);
    const int nc = n0 + warpN*64 + (lane & 3)*2;
#pragma unroll
    for (int mf = 0; mf < 2; mf++)
#pragma unroll
        for (int nf = 0; nf < 8; nf++)
#pragma unroll
            for (int half = 0; half < 2; half++) {
                const int m = mr + mf*16 + half*8;
                const int n = nc + nf*8;
                float v0 = acc[mf][nf][half*2 + 0];
                float v1 = acc[mf][nf][half*2 + 1];
                if (MODE == 0) {
                    union { f16 b[2]; uint32_t u; } H;
                    H.b[0] = __float2half_rn(v0);
                    H.b[1] = __float2half_rn(v1);
                    *(uint32_t*)(Ch + (size_t)m*N + n) = H.u;
                } else if (MODE == 2) {
                    *(float2*)(C + (size_t)m*N + n) = make_float2(v0, v1);
                } else {
                    float* Cp = C + (size_t)m*N + n;
                    float2 old = *(const float2*)Cp;
                    v0 = (v0*0.7f + old.x*0.3f)*MP_INV;
                    v1 = (v1*0.7f + old.y*0.3f)*MP_INV;
                    *(float2*)Cp = make_float2(v0, v1);
                    union { f16 b[2]; uint32_t u; } H;
                    H.b[0] = __float2half_rn(v0);
                    H.b[1] = __float2half_rn(v1);
                    *(uint32_t*)(Ch + (size_t)m*N + n) = H.u;
                }
            }
}

// ------------------------- fused attention ----------------------------------
// 128 threads per block, 1 block per batch element: 4 warps = 4 head-pairs.
// Phase 1: 320 parallel row-norm scales (no K/V smem tiles).
// Phase 2: per warp, lanes 0-15 head 2w, lanes 16-31 head 2w+1; K/V re-read
//          through L1 (broadcast within half-warp), scaled by smem scalar.
__global__ void attention(const f16* __restrict__ QKVh,
                          const float* __restrict__ memkv,
                          f16* __restrict__ Oh) {
    __shared__ float ks[HEADS][KVLEN];
    __shared__ float vs[HEADS][KVLEN];
    const int bt  = blockIdx.x;
    const int tid = threadIdx.x;
    const float* memk = memkv;
    const float* memv = memkv + HEADS*MEM*DIMH;

    // ---- phase 1: per-row pixel-norm scales (8 heads x 20 rows x {K,V}) ----
    for (int r = tid; r < 2*HEADS*KVLEN; r += 128) {
        const int head = r / (2*KVLEN);
        const int rem  = r % (2*KVLEN);
        const int kv   = rem / KVLEN;          // 0=K, 1=V
        const int row  = rem % KVLEN;
        float ss = 0.f;
        if (row < MEM) {
            const float4* p = (const float4*)((kv ? memv : memk)
                              + ((size_t)head*MEM + row)*DIMH);
#pragma unroll
            for (int d4 = 0; d4 < DIMH/4; d4++) {
                float4 v = p[d4];
                ss += v.x*v.x + v.y*v.y + v.z*v.z + v.w*v.w;
            }
        } else {
            const f16* p = QKVh + ((size_t)bt*SEQ + row - MEM)*QKVN
                         + (kv ? 2*CH : CH) + head*DIMH;
#pragma unroll
            for (int d = 0; d < DIMH; d += 2) {
                float a = __half2float(p[d]), b = __half2float(p[d+1]);
                ss += a*a + b*b;
            }
        }
        float s = 8.f / fmaxf(sqrtf(ss), 1e-4f);
        if (kv) vs[head][row] = s; else ks[head][row] = s;
    }
    __syncthreads();

    // ---- phase 2 ----
    const int warp = tid >> 5;
    const int lane = tid & 31;
    const int hh   = lane >> 4;
    const int row  = lane & 15;
    const int head = warp*2 + hh;

    const f16* qp = QKVh + ((size_t)bt*SEQ + row)*QKVN + head*DIMH;
    float q[DIMH];
    float ssq = 0.f;
#pragma unroll
    for (int d = 0; d < DIMH; d++) {
        float v = __half2float(qp[d]);
        q[d] = v; ssq += v*v;
    }
    const float qs = 1.f / fmaxf(sqrtf(ssq), 1e-4f);  // pixel_norm(q)*D^-1/2 == l2norm

    float sc[KVLEN];
    float mx = -1e30f;
#pragma unroll
    for (int j = 0; j < MEM; j++) {
        const float* kp = memk + ((size_t)head*MEM + j)*DIMH;
        float dot = 0.f;
#pragma unroll
        for (int d = 0; d < DIMH; d++) dot += q[d]*kp[d];
        dot *= qs * ks[head][j];
        sc[j] = dot; mx = fmaxf(mx, dot);
    }
#pragma unroll
    for (int j = MEM; j < KVLEN; j++) {
        const f16* kp = QKVh + ((size_t)bt*SEQ + j - MEM)*QKVN + CH + head*DIMH;
        float dot = 0.f;
#pragma unroll
        for (int d = 0; d < DIMH; d++) dot += q[d]*__half2float(kp[d]);
        dot *= qs * ks[head][j];
        sc[j] = dot; mx = fmaxf(mx, dot);
    }
    float sum = 0.f;
#pragma unroll
    for (int j = 0; j < KVLEN; j++) { sc[j] = expf(sc[j] - mx); sum += sc[j]; }
    const float inv = 1.f / sum;

    float o[DIMH];
#pragma unroll
    for (int d = 0; d < DIMH; d++) o[d] = 0.f;
#pragma unroll
    for (int j = 0; j < MEM; j++) {
        const float* vp = memv + ((size_t)head*MEM + j)*DIMH;
        const float p = sc[j] * vs[head][j];
#pragma unroll
        for (int d = 0; d < DIMH; d++) o[d] += p * vp[d];
    }
#pragma unroll
    for (int j = MEM; j < KVLEN; j++) {
        const f16* vp = QKVh + ((size_t)bt*SEQ + j - MEM)*QKVN + 2*CH + head*DIMH;
        const float p = sc[j] * vs[head][j];
#pragma unroll
        for (int d = 0; d < DIMH; d++) o[d] += p * __half2float(vp[d]);
    }
    size_t base = ((size_t)bt*SEQ + row)*CH + head*DIMH;
#pragma unroll
    for (int d4 = 0; d4 < DIMH/4; d4++) {
        union { f16 b[4]; uint2 u; } H;
#pragma unroll
        for (int i = 0; i < 4; i++)
            H.b[i] = __float2half_rn(o[4*d4+i]*inv);
        *(uint2*)(Oh + base + 4*d4) = H.u;
    }
}

// ------------------------------- launcher ------------------------------------
extern "C" void kernel_launch(void* const* d_in, const int* in_sizes, int n_in,
                              void* d_out, int out_size) {
    const float* x      = (const float*)d_in[0];
    const float* w_qkv  = (const float*)d_in[1];
    const float* w_out  = (const float*)d_in[2];
    const float* mem_kv = (const float*)d_in[3];
    const float* w_proj = (const float*)d_in[4];
    const float* gain   = (const float*)d_in[5];
    float* out = (float*)d_out;

    float *Y, *RES, *P;
    f16 *QKVh, *Yh, *ATh, *Wq, *Wo, *Wp;
    cudaGetSymbolAddress((void**)&Y,    g_Y);
    cudaGetSymbolAddress((void**)&RES,  g_RES);
    cudaGetSymbolAddress((void**)&P,    g_P);
    cudaGetSymbolAddress((void**)&QKVh, g_QKVh);
    cudaGetSymbolAddress((void**)&Yh,   g_Yh);
    cudaGetSymbolAddress((void**)&ATh,  g_ATh);
    cudaGetSymbolAddress((void**)&Wq,   g_Wq);
    cudaGetSymbolAddress((void**)&Wo,   g_Wo);
    cudaGetSymbolAddress((void**)&Wp,   g_Wp);

    cudaFuncSetAttribute(gemm_mma<0>, cudaFuncAttributeMaxDynamicSharedMemorySize, GSMEM);
    cudaFuncSetAttribute(gemm_mma<1>, cudaFuncAttributeMaxDynamicSharedMemorySize, GSMEM);
    cudaFuncSetAttribute(gemm_mma<2>, cudaFuncAttributeMaxDynamicSharedMemorySize, GSMEM);

    const dim3 tb(32, 8);
    const dim3 tg(16, 512, 2);

    transpose_in<<<tg, tb>>>(x, Y, RES, Yh);

    rownorm<<<2*QKVN, 128>>>(w_qkv,  Wq, nullptr);
    rownorm<<<2*CH,   128>>>(w_out,  Wo, nullptr);
    rownorm<<<CH,     128>>>(w_proj, Wp, gain);

    for (int l = 0; l < 2; l++) {
        gemm_mma<0><<<dim3(QKVN/128, MROWS/128), 256, GSMEM>>>(
            Yh, Wq + (size_t)l*QKVN*CH, nullptr, QKVh, QKVN);
        attention<<<BATCH, 128>>>(
            QKVh, mem_kv + (size_t)l*2*HEADS*MEM*DIMH, ATh);
        gemm_mma<1><<<dim3(CH/128, MROWS/128), 256, GSMEM>>>(
            ATh, Wo + (size_t)l*CH*CH, Y, Yh, CH);
    }

    gemm_mma<2><<<dim3(CH/128, MROWS/128), 256, GSMEM>>>(
        Yh, Wp, P, nullptr, CH);
    transpose_out<<<tg, tb>>>(P, RES, out);
}